// round 11
// baseline (speedup 1.0000x reference)
#include <cuda_runtime.h>

#define NB      160            // 5*32 boxes per batch
#define NT      256
#define RSPLIT  16
#define ROWS    32             // rows per CTA
#define MW      17             // padded mask row stride (words) -> conflict-free
#define NCTAS   (64 * RSPLIT)

__device__ float    g_part[64][RSPLIT][4];  // [tanh_sum, painted_tanh_sum, count]
__device__ unsigned g_count = 0;            // self-resetting last-CTA counter

// hardware tanh: 1 MUFU op
__device__ __forceinline__ float htanh(float x) {
    float t;
    asm("tanh.approx.f32 %0, %1;" : "=f"(t) : "f"(x));
    return t;
}

__global__ void __launch_bounds__(NT, 5)
mml_fused(const float* __restrict__ pred, const int* __restrict__ tgt,
          float* __restrict__ out)
{
    const int b    = blockIdx.x;
    const int seg  = blockIdx.y;
    const int row0 = seg * ROWS;
    const int tid  = threadIdx.x;
    const int lane = tid & 31;
    const int warp = tid >> 5;

    __shared__ int4     cbox[NB];          // compacted: (r0loc, r1loc, y1, y2)
    __shared__ int      s_nbox;
    __shared__ unsigned sm[ROWS * MW];     // padded mask tile
    __shared__ float    red[3][NT / 32];
    __shared__ float    shl[64];
    __shared__ bool     isLast;

    // ---- prefetch: start HBM streaming under the prologue's shadow ----
    const float4* p = (const float4*)(pred + ((size_t)b * 512 + row0) * 512);
    float4 pv0 = p[tid];
    float4 pv1 = p[tid + NT];
    float4 pv2 = p[tid + 2 * NT];
    float4 pv3 = p[tid + 3 * NT];

    // box load overlaps smem zeroing
    const int4* tb = (const int4*)(tgt + (size_t)b * NB * 4);
    int4 mybox;
    if (tid < NB) mybox = tb[tid];

    if (tid == 0) s_nbox = 0;
    for (int i = tid; i < ROWS * MW; i += NT) sm[i] = 0u;
    __syncthreads();

    // ---- compact boxes intersecting this 32-row segment ----
    if (tid < NB) {
        int x1 = min(mybox.x, 512),           y1 = min(mybox.y, 512);
        int x2 = min(mybox.x + mybox.z, 512), y2 = min(mybox.y + mybox.w, 512);
        if (x2 > row0 && x1 < row0 + ROWS && y2 > y1) {
            int slot = atomicAdd(&s_nbox, 1);
            cbox[slot] = make_int4(max(x1 - row0, 0), min(x2 - row0, ROWS), y1, y2);
        }
    }
    __syncthreads();
    const int nbox = s_nbox;

    // ---- warp-per-box paint: lane = row, padded stride -> 32 distinct banks ----
    for (int i = warp; i < nbox; i += NT / 32) {
        int4 bx = cbox[i];
        int wlo = bx.z >> 5, whi = (bx.w - 1) >> 5;
        unsigned loMask = ~((1u << (bx.z & 31)) - 1u);
        unsigned hiMask = 0xFFFFFFFFu >> (31 - ((bx.w - 1) & 31));
        int r = bx.x + lane;
        if (r < bx.y) {
            unsigned* mrow = &sm[r * MW];
            for (int w = wlo; w <= whi; w++) {
                unsigned bits = 0xFFFFFFFFu;
                if (w == wlo) bits &= loMask;
                if (w == whi) bits &= hiMask;
                atomicOr(&mrow[w], bits);
            }
        }
    }
    __syncthreads();

    // ---- exact painted count: thread owns cells tid and tid+256 ----
    float cntf;
    {
        int c0 = tid, c1 = tid + NT;
        cntf = (float)(__popc(sm[(c0 >> 4) * MW + (c0 & 15)]) +
                       __popc(sm[(c1 >> 4) * MW + (c1 & 15)]));
    }

    // ---- prepack this thread's 16 mask nibbles into two u32 regs ----
    const int c4   = tid & 127;
    const int wofs = c4 >> 3;
    const int msh  = (c4 & 7) * 4;
    const int rb   = tid >> 7;                 // 0 or 1
    unsigned mlo = 0u, mhi = 0u;
    #pragma unroll
    for (int k = 0; k < 8; k++) {
        mlo |= ((sm[(rb + 2 * k) * MW + wofs] >> msh) & 0xFu) << (4 * k);
        mhi |= ((sm[(rb + 2 * (k + 8)) * MW + wofs] >> msh) & 0xFu) << (4 * k);
    }

    // ---- streaming: sigmoid = 0.5*tanh(x/2)+0.5, constants folded out.
    //      Coherent-mask fast path: full/empty nibbles reuse the tsum pair sums.
    float tsum = 0.f, ti0 = 0.f, ti1 = 0.f;
#define STREAM_BODY(v, mw)                                                 \
    {   float t0 = htanh(0.5f * (v).x), t1 = htanh(0.5f * (v).y);          \
        float t2 = htanh(0.5f * (v).z), t3 = htanh(0.5f * (v).w);          \
        float s01 = t0 + t1, s23 = t2 + t3, s = s01 + s23;                 \
        tsum += s;                                                         \
        if ((mw) == 0xFu)      ti0 += s;                                   \
        else if ((mw) != 0u) {                                             \
            if ((mw) & 1u) ti0 += t0;                                      \
            if ((mw) & 2u) ti1 += t1;                                      \
            if ((mw) & 4u) ti0 += t2;                                      \
            if ((mw) & 8u) ti1 += t3;                                      \
        } }

    STREAM_BODY(pv0, (mlo      ) & 0xFu);
    STREAM_BODY(pv1, (mlo >>  4) & 0xFu);
    STREAM_BODY(pv2, (mlo >>  8) & 0xFu);
    STREAM_BODY(pv3, (mlo >> 12) & 0xFu);
    #pragma unroll
    for (int k = 4; k < 8; k++) {
        float4 v = p[tid + NT * k];
        STREAM_BODY(v, (mlo >> (4 * k)) & 0xFu);
    }
    #pragma unroll
    for (int k = 8; k < 16; k++) {
        float4 v = p[tid + NT * k];
        STREAM_BODY(v, (mhi >> (4 * (k - 8))) & 0xFu);
    }
    float tisum = ti0 + ti1;

    // ---- block reduce ----
    #pragma unroll
    for (int off = 16; off; off >>= 1) {
        tsum  += __shfl_down_sync(0xffffffffu, tsum,  off);
        tisum += __shfl_down_sync(0xffffffffu, tisum, off);
        cntf  += __shfl_down_sync(0xffffffffu, cntf,  off);
    }
    if (lane == 0) { red[0][warp] = tsum; red[1][warp] = tisum; red[2][warp] = cntf; }
    __syncthreads();
    if (tid == 0) {
        float T = 0.f, TI = 0.f, C = 0.f;
        #pragma unroll
        for (int w = 0; w < NT / 32; w++) { T += red[0][w]; TI += red[1][w]; C += red[2][w]; }
        g_part[b][seg][0] = T;
        g_part[b][seg][1] = TI;
        g_part[b][seg][2] = C;
        __threadfence();
        unsigned prev = atomicAdd(&g_count, 1u);
        isLast = (prev == NCTAS - 1);
        if (isLast) g_count = 0;               // self-reset for graph replay
    }
    __syncthreads();

    // ---- fused final dice: all 256 threads, float4 ldcv, width-4 shuffle ----
    if (isLast) {
        __threadfence();
        const int batch = tid >> 2;            // 0..63
        const int q     = tid & 3;             // 4 segments each
        float T = 0.f, TI = 0.f, C = 0.f;
        const float4* gp4 = (const float4*)&g_part[batch][q * 4][0];
        #pragma unroll
        for (int j = 0; j < 4; j++) {
            float4 v = __ldcv(gp4 + j);
            T += v.x; TI += v.y; C += v.z;
        }
        T  += __shfl_down_sync(0xffffffffu, T,  2);
        TI += __shfl_down_sync(0xffffffffu, TI, 2);
        C  += __shfl_down_sync(0xffffffffu, C,  2);
        T  += __shfl_down_sync(0xffffffffu, T,  1);
        TI += __shfl_down_sync(0xffffffffu, TI, 1);
        C  += __shfl_down_sync(0xffffffffu, C,  1);
        if (q == 0) {
            // unfold: P = 0.5*T + 0.5*512*512 ; I = 0.5*TI + 0.5*C
            float P = 0.5f * T + 131072.0f;
            float I = 0.5f * TI + 0.5f * C;
            float inter = 255.f * I;
            shl[batch] = (inter + 1.f) / (P + 255.f * C - inter + 1.f);
        }
        __syncthreads();
        #pragma unroll
        for (int off = 32; off; off >>= 1) {
            if (tid < off && tid + off < 64) shl[tid] += shl[tid + off];
            __syncthreads();
        }
        if (tid == 0) out[0] = 1.0f - shl[0] * (1.0f / 64.0f);
    }
}

extern "C" void kernel_launch(void* const* d_in, const int* in_sizes, int n_in,
                              void* d_out, int out_size) {
    const float* pred = (const float*)d_in[0];   // (64,1,512,512) fp32
    const int*   tgt  = (const int*)d_in[1];     // (64,5,32,4) int32
    float* out = (float*)d_out;                  // scalar

    mml_fused<<<dim3(64, RSPLIT), NT>>>(pred, tgt, out);
}